// round 8
// baseline (speedup 1.0000x reference)
#include <cuda_runtime.h>
#include <math.h>

#define TS 512
#define BN 128
#define IND 32
#define HN 512
#define ON 8
#define PN 64

// FX[t,b,h] = sum_i Win[h,i]*x[t,b,i]  (134 MB scratch)
__device__ float g_fx[(size_t)TS * BN * HN];
// Wr in h-pair/j-pair interleaved layout: ulonglong2 at [j2*256 + hp] =
// ( W[h0][j], W[h1][j] | W[h0][j+1], W[h1][j+1] ),  h0=2*hp, j=2*j2.
__device__ float g_wr2[(size_t)HN * HN];

typedef unsigned long long ull;

__device__ __forceinline__ ull ffma2(ull a, ull b, ull c) {
    ull d; asm("fma.rn.f32x2 %0,%1,%2,%3;" : "=l"(d) : "l"(a), "l"(b), "l"(c)); return d;
}
__device__ __forceinline__ ull pk2(float x, float y) {
    ull d; asm("mov.b64 %0,{%1,%2};" : "=l"(d) : "f"(x), "f"(y)); return d;
}
__device__ __forceinline__ void unpk2(ull a, float& lo, float& hi) {
    asm("mov.b64 {%0,%1},%2;" : "=f"(lo), "=f"(hi) : "l"(a));
}
__device__ __forceinline__ unsigned smem_u32(const void* p) {
    unsigned a;
    asm("{ .reg .u64 t; cvta.to.shared.u64 t, %1; cvt.u32.u64 %0, t; }"
        : "=r"(a) : "l"(p));
    return a;
}

// ---------------------------------------------------------------------------
// Kernel 1: FX = x @ Win^T, strict sequential-k FMA chain (bit-locked).
// ---------------------------------------------------------------------------
__global__ void __launch_bounds__(512, 1)
fx_kernel(const float* __restrict__ x, const float* __restrict__ Win) {
    __shared__ __align__(16) float xs[64 * IND];
    const int tid = threadIdx.x;

    float w[32];
    const float4* wr4 = (const float4*)(Win + tid * IND);
#pragma unroll
    for (int k = 0; k < 8; k++) {
        float4 f = wr4[k];
        w[4 * k + 0] = f.x; w[4 * k + 1] = f.y;
        w[4 * k + 2] = f.z; w[4 * k + 3] = f.w;
    }

    const int pair0 = blockIdx.x * 64;
    ((float4*)xs)[tid] = ((const float4*)(x + (size_t)pair0 * IND))[tid];
    __syncthreads();

    float* outp = g_fx + (size_t)pair0 * HN + tid;
#pragma unroll 4
    for (int k = 0; k < 64; k++) {
        const float* xk = xs + k * IND;
        float acc = 0.0f;
#pragma unroll
        for (int i = 0; i < IND; i++) acc = __fmaf_rn(w[i], xk[i], acc);
        outp[(size_t)k * HN] = acc;
    }
}

// ---------------------------------------------------------------------------
// Kernel 2: Wr[h][j] via sequential-p chain (bit-locked), h/j-pair interleaved.
// ---------------------------------------------------------------------------
__global__ void __launch_bounds__(512, 1)
wr_kernel(const float* __restrict__ pin, const float* __restrict__ pout,
          const float* __restrict__ l) {
    __shared__ float lp[PN];
    const int h = blockIdx.x;
    const int j = threadIdx.x;
    if (j < PN) lp[j] = __fmul_rn(l[j], pin[h * PN + j]);
    __syncthreads();

    const float* pr = pout + j * PN;
    float acc = 0.0f;
#pragma unroll
    for (int p = 0; p < PN; p++) acc = __fmaf_rn(lp[p], pr[p], acc);

    const size_t q4 = (size_t)(j >> 1) * 256 + (h >> 1);
    g_wr2[q4 * 4 + (h & 1) + 2 * (j & 1)] = acc;
}

// ---------------------------------------------------------------------------
// Kernel 3: scan. Cluster of 8 CTAs = 8 batches; CTA u holds Wr rows
// h in [u*64, u*64+64) in SMEM (128 KB). Thread = (h-pair, batch-pair):
// 32 hp x 4 bp = 128 threads, two FFMA2 chains each (bit-exact order).
// r exchanged per step via DSMEM pair-push, double-buffered, 1 cluster barrier.
// ---------------------------------------------------------------------------
__global__ void __launch_bounds__(128, 1) __cluster_dims__(8, 1, 1)
snn_kernel(const float* __restrict__ Wout, float* __restrict__ out,
           float arg_ls, float arg_lm, float arg_ld,
           float rgain, float dtc, float tref)
{
    extern __shared__ __align__(16) unsigned char smraw[];
    ulonglong2* wr2_s = (ulonglong2*)smraw;                      // 8192 x 16B
    ull (*rdup)[8][HN] = (ull(*)[8][HN])(smraw + 131072);        // [2][8][512]
    float* wout_sh = (float*)(smraw + 196608);                   // 4096 floats
    float* part_y  = (float*)(smraw + 212992);                   // 64 floats

    const int tid = threadIdx.x;
    unsigned u;
    asm("mov.u32 %0, %%cluster_ctarank;" : "=r"(u));
    const int cl   = blockIdx.x >> 3;      // cluster id
    const int base = cl * 8;               // first batch of this cluster

    const float ls  = expf(arg_ls);
    const float lm  = expf(arg_lm);
    const float ldc = expf(arg_ld);
    const float olm = 1.0f - lm;

    // lane layout: warp w holds hp = w*8 + (ln&7), bp = ln>>3
    const int w  = tid >> 5, ln = tid & 31;
    const int hp = w * 8 + (ln & 7);       // 0..31 (local h-pair)
    const int bp = ln >> 3;                // 0..3  (batch pair)
    const int hg0 = (int)u * 64 + 2 * hp;  // global h of lane-low

    // stage Wr slice (rows u*64 .. u*64+63), j2-major: wr2_s[j2*32 + hp]
    {
        const ulonglong2* gw = (const ulonglong2*)g_wr2;
        for (int i = tid; i < 8192; i += 128) {
            int j2 = i >> 5, ll = i & 31;
            wr2_s[i] = gw[(size_t)j2 * 256 + u * 32 + ll];
        }
    }
    for (int i = tid; i < HN * ON; i += 128)
        wout_sh[i] = Wout[(i & 7) * HN + (i >> 3)];
    // zero parity-0 r buffers (all 8 batches)
    for (int i = tid; i < 8 * HN; i += 128) ((ull*)rdup)[i] = 0ull;

    // DSMEM bases of rdup in every cluster CTA (incl. self)
    unsigned rd_base[8];
    {
        const unsigned rd_local = smem_u32(&rdup[0][0][0]);
#pragma unroll
        for (int k = 0; k < 8; k++)
            asm("mapa.shared::cluster.u32 %0,%1,%2;"
                : "=r"(rd_base[k]) : "r"(rd_local), "r"(k));
    }

    // neuron state: [hh][bb]
    float I[2][2]   = {{0.f,0.f},{0.f,0.f}};
    float mem[2][2] = {{0.f,0.f},{0.f,0.f}};
    float s[2][2]   = {{0.f,0.f},{0.f,0.f}};
    float r[2][2]   = {{0.f,0.f},{0.f,0.f}};
    float tl[2][2]  = {{-1.f,-1.f},{-1.f,-1.f}};

    const int b0g = base + 2 * bp, b1g = b0g + 1;
    const float2* fx0 = (const float2*)(g_fx + (size_t)b0g * HN + hg0);
    const float2* fx1 = (const float2*)(g_fx + (size_t)b1g * HN + hg0);
    float2 fxc0 = fx0[0], fxc1 = fx1[0];

    __syncthreads();
    // init visible cluster-wide before any peer pushes can land
    asm volatile("barrier.cluster.arrive.aligned;" ::: "memory");
    asm volatile("barrier.cluster.wait.aligned;"   ::: "memory");

#pragma unroll 1
    for (int t = 0; t < TS; t++) {
        const int par = t & 1, pn = par ^ 1;
        const int tn = (t < TS - 1) ? t + 1 : t;
        const float2 fxn0 = fx0[(size_t)tn * (BN * HN / 2)];
        const float2 fxn1 = fx1[(size_t)tn * (BN * HN / 2)];

        // two FFMA2 chains, sequential in j (bit-exact vs scalar chain)
        const ulonglong2* d0 = (const ulonglong2*)&rdup[par][2 * bp][0];
        const ulonglong2* d1 = (const ulonglong2*)&rdup[par][2 * bp + 1][0];
        ull rec_b0 = 0ull, rec_b1 = 0ull;
#pragma unroll 8
        for (int j2 = 0; j2 < 256; j2++) {
            const ulonglong2 q  = wr2_s[j2 * 32 + hp];
            const ulonglong2 r0 = d0[j2];
            const ulonglong2 r1 = d1[j2];
            rec_b0 = ffma2(q.x, r0.x, rec_b0);
            rec_b0 = ffma2(q.y, r0.y, rec_b0);
            rec_b1 = ffma2(q.x, r1.x, rec_b1);
            rec_b1 = ffma2(q.y, r1.y, rec_b1);
        }
        float rec[2][2], fxv[2][2];
        unpk2(rec_b0, rec[0][0], rec[1][0]);
        unpk2(rec_b1, rec[0][1], rec[1][1]);
        fxv[0][0] = fxc0.x; fxv[1][0] = fxc0.y;
        fxv[0][1] = fxc1.x; fxv[1][1] = fxc1.y;

        const float ti = __fmul_rn(dtc, (float)t);
#pragma unroll
        for (int hh = 0; hh < 2; hh++)
#pragma unroll
            for (int bb = 0; bb < 2; bb++) {
                I[hh][bb] = __fadd_rn(__fadd_rn(__fmul_rn(ls, I[hh][bb]),
                                                fxv[hh][bb]), rec[hh][bb]);
                const float notref = (ti > __fadd_rn(tl[hh][bb], tref)) ? 1.0f : 0.0f;
                const float memn = __fmul_rn(__fmul_rn(notref,
                        __fadd_rn(__fmul_rn(lm, mem[hh][bb]),
                                  __fmul_rn(olm, I[hh][bb]))),
                        __fsub_rn(1.0f, s[hh][bb]));
                r[hh][bb] = __fadd_rn(__fmul_rn(ldc, r[hh][bb]),
                                      __fmul_rn(rgain, s[hh][bb]));
                const float snew = (__fsub_rn(memn, 1.0f) > 0.0f) ? 1.0f : 0.0f;
                tl[hh][bb] = __fadd_rn(tl[hh][bb],
                               __fmul_rn(__fsub_rn(ti, tl[hh][bb]), snew));
                mem[hh][bb] = memn; s[hh][bb] = snew;
            }
        fxc0 = fxn0; fxc1 = fxn1;

        // publish r(t) pairs into parity pn of EVERY cluster CTA
#pragma unroll
        for (int bb = 0; bb < 2; bb++)
#pragma unroll
            for (int hh = 0; hh < 2; hh++) {
                const ull v = pk2(r[hh][bb], r[hh][bb]);
                const unsigned off =
                    (((unsigned)pn * 8 + (2 * bp + bb)) * HN + hg0 + hh) * 8u;
#pragma unroll
                for (int k = 0; k < 8; k++)
                    asm volatile("st.shared::cluster.b64 [%0], %1;"
                                 :: "r"(rd_base[k] + off), "l"(v) : "memory");
            }
        asm volatile("barrier.cluster.arrive.aligned;" ::: "memory");
        asm volatile("barrier.cluster.wait.aligned;"   ::: "memory");

        // y for batch (base+u) from full r(t) (same order as R6/R7)
        if (tid < 64) {
            const int o = tid & 7, seg = tid >> 3;
            const float* wq = wout_sh + (seg << 6) * 8 + o;
            const float* rr = (const float*)&rdup[pn][u][seg << 6];
            float e0 = 0.0f, e1 = 0.0f;
#pragma unroll
            for (int hh = 0; hh < 64; hh += 2) {
                e0 = __fmaf_rn(wq[hh << 3],       rr[hh * 2],       e0);
                e1 = __fmaf_rn(wq[(hh + 1) << 3], rr[(hh + 1) * 2], e1);
            }
            part_y[tid] = e0 + e1;
        }
        __syncthreads();
        if (tid < ON) {
            const float* q = part_y + tid;
            float v = ((q[0] + q[8]) + (q[16] + q[24])) +
                      ((q[32] + q[40]) + (q[48] + q[56]));
            out[((size_t)t * BN + base + u) * ON + tid] = v;
        }
    }
}

extern "C" void kernel_launch(void* const* d_in, const int* in_sizes, int n_in,
                              void* d_out, int out_size) {
    const float* x    = (const float*)d_in[0];
    const float* Win  = (const float*)d_in[1];
    const float* Wout = (const float*)d_in[2];
    const float* pin  = (const float*)d_in[3];
    const float* pout = (const float*)d_in[4];
    const float* l    = (const float*)d_in[5];
    float* out = (float*)d_out;

    const float arg_ls = (float)(-0.002 / 0.01);
    const float arg_lm = (float)(-0.002 / 0.02);
    const float arg_ld = (float)(-0.002 / 0.03);
    const float rgain  = (float)(0.002 / 0.03);
    const float dtc    = (float)0.002;
    const float tref   = (float)(5.0 * 0.002);

    const int smem_bytes = 131072 + 65536 + 16384 + 256;   // 213248
    cudaFuncSetAttribute(snn_kernel, cudaFuncAttributeMaxDynamicSharedMemorySize,
                         smem_bytes);

    fx_kernel<<<(TS * BN) / 64, 512>>>(x, Win);
    wr_kernel<<<HN, 512>>>(pin, pout, l);
    snn_kernel<<<BN, 128, smem_bytes>>>(Wout, out, arg_ls, arg_lm, arg_ld,
                                        rgain, dtc, tref);
}

// round 9
// speedup vs baseline: 1.2242x; 1.2242x over previous
#include <cuda_runtime.h>
#include <math.h>

#define TS 512
#define BN 128
#define IND 32
#define HN 512
#define ON 8
#define PN 64

// FX[t,b,h] = sum_i Win[h,i]*x[t,b,i]  (134 MB scratch)
__device__ float g_fx[(size_t)TS * BN * HN];
// Wr in h-pair/j-pair interleaved layout: ulonglong2 at [j2*256 + hp] =
// ( W[h0][j], W[h1][j] | W[h0][j+1], W[h1][j+1] ),  h0=2*hp, j=2*j2.
__device__ float g_wr2[(size_t)HN * HN];
// per-cluster r exchange buffer: [cluster][parity][batch][h]
__device__ float g_r[16 * 2 * 8 * HN];

typedef unsigned long long ull;

__device__ __forceinline__ ull ffma2(ull a, ull b, ull c) {
    ull d; asm("fma.rn.f32x2 %0,%1,%2,%3;" : "=l"(d) : "l"(a), "l"(b), "l"(c)); return d;
}
__device__ __forceinline__ ull pk2(float x, float y) {
    ull d; asm("mov.b64 %0,{%1,%2};" : "=l"(d) : "f"(x), "f"(y)); return d;
}
__device__ __forceinline__ void unpk2(ull a, float& lo, float& hi) {
    asm("mov.b64 {%0,%1},%2;" : "=f"(lo), "=f"(hi) : "l"(a));
}

// ---------------------------------------------------------------------------
// Kernel 1: FX = x @ Win^T, strict sequential-k FMA chain (bit-locked).
// ---------------------------------------------------------------------------
__global__ void __launch_bounds__(512, 1)
fx_kernel(const float* __restrict__ x, const float* __restrict__ Win) {
    __shared__ __align__(16) float xs[64 * IND];
    const int tid = threadIdx.x;

    float w[32];
    const float4* wr4 = (const float4*)(Win + tid * IND);
#pragma unroll
    for (int k = 0; k < 8; k++) {
        float4 f = wr4[k];
        w[4 * k + 0] = f.x; w[4 * k + 1] = f.y;
        w[4 * k + 2] = f.z; w[4 * k + 3] = f.w;
    }

    const int pair0 = blockIdx.x * 64;
    ((float4*)xs)[tid] = ((const float4*)(x + (size_t)pair0 * IND))[tid];
    __syncthreads();

    float* outp = g_fx + (size_t)pair0 * HN + tid;
#pragma unroll 4
    for (int k = 0; k < 64; k++) {
        const float* xk = xs + k * IND;
        float acc = 0.0f;
#pragma unroll
        for (int i = 0; i < IND; i++) acc = __fmaf_rn(w[i], xk[i], acc);
        outp[(size_t)k * HN] = acc;
    }
}

// ---------------------------------------------------------------------------
// Kernel 2: Wr[h][j] via sequential-p chain (bit-locked), h/j-pair interleaved.
// ---------------------------------------------------------------------------
__global__ void __launch_bounds__(512, 1)
wr_kernel(const float* __restrict__ pin, const float* __restrict__ pout,
          const float* __restrict__ l) {
    __shared__ float lp[PN];
    const int h = blockIdx.x;
    const int j = threadIdx.x;
    if (j < PN) lp[j] = __fmul_rn(l[j], pin[h * PN + j]);
    __syncthreads();

    const float* pr = pout + j * PN;
    float acc = 0.0f;
#pragma unroll
    for (int p = 0; p < PN; p++) acc = __fmaf_rn(lp[p], pr[p], acc);

    const size_t q4 = (size_t)(j >> 1) * 256 + (h >> 1);
    g_wr2[q4 * 4 + (h & 1) + 2 * (j & 1)] = acc;
}

// ---------------------------------------------------------------------------
// Kernel 3: scan. Cluster of 8 CTAs = 8 batches; CTA u holds Wr rows
// h in [u*64, u*64+64) in SMEM (128 KB). Thread = (h-pair, batch-pair).
// r exchanged per step through L2 (STG -> cluster barrier -> __ldcg pull),
// NOT via DSMEM pushes (R8 lesson).
// ---------------------------------------------------------------------------
__global__ void __launch_bounds__(128, 1) __cluster_dims__(8, 1, 1)
snn_kernel(const float* __restrict__ Wout, float* __restrict__ out,
           float arg_ls, float arg_lm, float arg_ld,
           float rgain, float dtc, float tref)
{
    extern __shared__ __align__(16) unsigned char smraw[];
    ulonglong2* wr2_s = (ulonglong2*)smraw;                      // 8192 x 16B
    ull (*rdup)[8][HN] = (ull(*)[8][HN])(smraw + 131072);        // [2][8][512]
    float* wout_sh = (float*)(smraw + 196608);                   // 4096 floats
    float* part_y  = (float*)(smraw + 212992);                   // 64 floats

    const int tid = threadIdx.x;
    unsigned u;
    asm("mov.u32 %0, %%cluster_ctarank;" : "=r"(u));
    const int cl   = blockIdx.x >> 3;      // cluster id
    const int base = cl * 8;               // first batch of this cluster

    const float ls  = expf(arg_ls);
    const float lm  = expf(arg_lm);
    const float ldc = expf(arg_ld);
    const float olm = 1.0f - lm;

    // lane layout: warp w holds hp = w*8 + (ln&7), bp = ln>>3
    const int w  = tid >> 5, ln = tid & 31;
    const int hp = w * 8 + (ln & 7);       // 0..31 (local h-pair)
    const int bp = ln >> 3;                // 0..3  (batch pair)
    const int hg0 = (int)u * 64 + 2 * hp;  // global h of lane-low

    // stage Wr slice (rows u*64 .. u*64+63), j2-major: wr2_s[j2*32 + hp]
    {
        const ulonglong2* gw = (const ulonglong2*)g_wr2;
        for (int i = tid; i < 8192; i += 128) {
            int j2 = i >> 5, ll = i & 31;
            wr2_s[i] = gw[(size_t)j2 * 256 + u * 32 + ll];
        }
    }
    for (int i = tid; i < HN * ON; i += 128)
        wout_sh[i] = Wout[(i & 7) * HN + (i >> 3)];
    // zero parity-0 r buffers (all 8 batches)
    for (int i = tid; i < 8 * HN; i += 128) ((ull*)rdup)[i] = 0ull;

    // neuron state: [hh][bb]
    float I[2][2]   = {{0.f,0.f},{0.f,0.f}};
    float mem[2][2] = {{0.f,0.f},{0.f,0.f}};
    float s[2][2]   = {{0.f,0.f},{0.f,0.f}};
    float r[2][2]   = {{0.f,0.f},{0.f,0.f}};
    float tl[2][2]  = {{-1.f,-1.f},{-1.f,-1.f}};

    const int b0g = base + 2 * bp, b1g = b0g + 1;
    const float2* fx0 = (const float2*)(g_fx + (size_t)b0g * HN + hg0);
    const float2* fx1 = (const float2*)(g_fx + (size_t)b1g * HN + hg0);
    float2 fxc0 = fx0[0], fxc1 = fx1[0];

    float* gr_cl = g_r + (size_t)cl * 2 * 8 * HN;   // this cluster's buffer

    __syncthreads();

#pragma unroll 1
    for (int t = 0; t < TS; t++) {
        const int par = t & 1, pn = par ^ 1;
        const int tn = (t < TS - 1) ? t + 1 : t;
        const float2 fxn0 = fx0[(size_t)tn * (BN * HN / 2)];
        const float2 fxn1 = fx1[(size_t)tn * (BN * HN / 2)];

        // two FFMA2 chains, sequential in j (bit-exact vs scalar chain)
        const ulonglong2* d0 = (const ulonglong2*)&rdup[par][2 * bp][0];
        const ulonglong2* d1 = (const ulonglong2*)&rdup[par][2 * bp + 1][0];
        ull rec_b0 = 0ull, rec_b1 = 0ull;
#pragma unroll 8
        for (int j2 = 0; j2 < 256; j2++) {
            const ulonglong2 q  = wr2_s[j2 * 32 + hp];
            const ulonglong2 r0 = d0[j2];
            const ulonglong2 r1 = d1[j2];
            rec_b0 = ffma2(q.x, r0.x, rec_b0);
            rec_b0 = ffma2(q.y, r0.y, rec_b0);
            rec_b1 = ffma2(q.x, r1.x, rec_b1);
            rec_b1 = ffma2(q.y, r1.y, rec_b1);
        }
        float rec[2][2], fxv[2][2];
        unpk2(rec_b0, rec[0][0], rec[1][0]);
        unpk2(rec_b1, rec[0][1], rec[1][1]);
        fxv[0][0] = fxc0.x; fxv[1][0] = fxc0.y;
        fxv[0][1] = fxc1.x; fxv[1][1] = fxc1.y;

        const float ti = __fmul_rn(dtc, (float)t);
#pragma unroll
        for (int hh = 0; hh < 2; hh++)
#pragma unroll
            for (int bb = 0; bb < 2; bb++) {
                I[hh][bb] = __fadd_rn(__fadd_rn(__fmul_rn(ls, I[hh][bb]),
                                                fxv[hh][bb]), rec[hh][bb]);
                const float notref = (ti > __fadd_rn(tl[hh][bb], tref)) ? 1.0f : 0.0f;
                const float memn = __fmul_rn(__fmul_rn(notref,
                        __fadd_rn(__fmul_rn(lm, mem[hh][bb]),
                                  __fmul_rn(olm, I[hh][bb]))),
                        __fsub_rn(1.0f, s[hh][bb]));
                r[hh][bb] = __fadd_rn(__fmul_rn(ldc, r[hh][bb]),
                                      __fmul_rn(rgain, s[hh][bb]));
                const float snew = (__fsub_rn(memn, 1.0f) > 0.0f) ? 1.0f : 0.0f;
                tl[hh][bb] = __fadd_rn(tl[hh][bb],
                               __fmul_rn(__fsub_rn(ti, tl[hh][bb]), snew));
                mem[hh][bb] = memn; s[hh][bb] = snew;
            }
        fxc0 = fxn0; fxc1 = fxn1;

        // publish r(t): 2 coalesced STG.64 into this cluster's L2 buffer
        {
            float* dst = gr_cl + ((size_t)pn * 8 + 2 * bp) * HN + hg0;
            *(float2*)dst        = make_float2(r[0][0], r[1][0]);
            *(float2*)(dst + HN) = make_float2(r[0][1], r[1][1]);
        }

        // cluster barrier: release STGs, acquire peers' STGs
        asm volatile("barrier.cluster.arrive.aligned;" ::: "memory");
        asm volatile("barrier.cluster.wait.aligned;"   ::: "memory");

        // pull full r-set (8 batches x 512 h = 16 KB) from L2, store dup pairs
        {
            const float4* src = (const float4*)(gr_cl + (size_t)pn * 8 * HN);
            float4 v[8];
#pragma unroll
            for (int i = 0; i < 8; i++) v[i] = __ldcg(src + tid + i * 128);
            ulonglong2* dst2 = (ulonglong2*)&rdup[pn][0][0];
#pragma unroll
            for (int i = 0; i < 8; i++) {
                const int idx = tid + i * 128;
                dst2[idx * 2 + 0] = make_ulonglong2(pk2(v[i].x, v[i].x),
                                                    pk2(v[i].y, v[i].y));
                dst2[idx * 2 + 1] = make_ulonglong2(pk2(v[i].z, v[i].z),
                                                    pk2(v[i].w, v[i].w));
            }
        }
        __syncthreads();   // rdup[pn] complete

        // y for batch (base+u) from full r(t) (same order as R6/R7/R8)
        if (tid < 64) {
            const int o = tid & 7, seg = tid >> 3;
            const float* wq = wout_sh + (seg << 6) * 8 + o;
            const float* rr = (const float*)&rdup[pn][u][seg << 6];
            float e0 = 0.0f, e1 = 0.0f;
#pragma unroll
            for (int hh = 0; hh < 64; hh += 2) {
                e0 = __fmaf_rn(wq[hh << 3],       rr[hh * 2],       e0);
                e1 = __fmaf_rn(wq[(hh + 1) << 3], rr[(hh + 1) * 2], e1);
            }
            part_y[tid] = e0 + e1;
        }
        __syncthreads();
        if (tid < ON) {
            const float* q = part_y + tid;
            float v = ((q[0] + q[8]) + (q[16] + q[24])) +
                      ((q[32] + q[40]) + (q[48] + q[56]));
            out[((size_t)t * BN + base + u) * ON + tid] = v;
        }
    }
}

extern "C" void kernel_launch(void* const* d_in, const int* in_sizes, int n_in,
                              void* d_out, int out_size) {
    const float* x    = (const float*)d_in[0];
    const float* Win  = (const float*)d_in[1];
    const float* Wout = (const float*)d_in[2];
    const float* pin  = (const float*)d_in[3];
    const float* pout = (const float*)d_in[4];
    const float* l    = (const float*)d_in[5];
    float* out = (float*)d_out;

    const float arg_ls = (float)(-0.002 / 0.01);
    const float arg_lm = (float)(-0.002 / 0.02);
    const float arg_ld = (float)(-0.002 / 0.03);
    const float rgain  = (float)(0.002 / 0.03);
    const float dtc    = (float)0.002;
    const float tref   = (float)(5.0 * 0.002);

    const int smem_bytes = 131072 + 65536 + 16384 + 256;   // 213248
    cudaFuncSetAttribute(snn_kernel, cudaFuncAttributeMaxDynamicSharedMemorySize,
                         smem_bytes);

    fx_kernel<<<(TS * BN) / 64, 512>>>(x, Win);
    wr_kernel<<<HN, 512>>>(pin, pout, l);
    snn_kernel<<<BN, 128, smem_bytes>>>(Wout, out, arg_ls, arg_lm, arg_ld,
                                        rgain, dtc, tref);
}

// round 10
// speedup vs baseline: 2.1094x; 1.7231x over previous
#include <cuda_runtime.h>
#include <math.h>

#define TS 512
#define BN 128
#define IND 32
#define HN 512
#define ON 8
#define PN 64

// FX[t,b,h] = sum_i Win[h,i]*x[t,b,i]  (134 MB scratch)
__device__ float g_fx[(size_t)TS * BN * HN];
// Wr in h-pair/j-pair interleaved layout: ulonglong2 at [j2*256 + hp] =
// ( W[h0][j], W[h1][j] | W[h0][j+1], W[h1][j+1] ),  h0=2*hp, j=2*j2.
__device__ float g_wr2[(size_t)HN * HN];
// per-group r exchange buffer: [group][parity][batch][h]
__device__ float g_r[16 * 2 * 8 * HN];
// software barrier state (zero-init; reset at kernel end -> replay-safe)
__device__ unsigned g_sync[16][8 * 32];   // step counters, sector-padded
__device__ unsigned g_fin[16 * 32];       // finish counters, sector-padded

typedef unsigned long long ull;

__device__ __forceinline__ ull ffma2(ull a, ull b, ull c) {
    ull d; asm("fma.rn.f32x2 %0,%1,%2,%3;" : "=l"(d) : "l"(a), "l"(b), "l"(c)); return d;
}
__device__ __forceinline__ ull pk2(float x, float y) {
    ull d; asm("mov.b64 %0,{%1,%2};" : "=l"(d) : "f"(x), "f"(y)); return d;
}
__device__ __forceinline__ void unpk2(ull a, float& lo, float& hi) {
    asm("mov.b64 {%0,%1},%2;" : "=f"(lo), "=f"(hi) : "l"(a));
}

// ---------------------------------------------------------------------------
// Kernel 1: FX = x @ Win^T, strict sequential-k FMA chain (bit-locked).
// ---------------------------------------------------------------------------
__global__ void __launch_bounds__(512, 1)
fx_kernel(const float* __restrict__ x, const float* __restrict__ Win) {
    __shared__ __align__(16) float xs[64 * IND];
    const int tid = threadIdx.x;

    float w[32];
    const float4* wr4 = (const float4*)(Win + tid * IND);
#pragma unroll
    for (int k = 0; k < 8; k++) {
        float4 f = wr4[k];
        w[4 * k + 0] = f.x; w[4 * k + 1] = f.y;
        w[4 * k + 2] = f.z; w[4 * k + 3] = f.w;
    }

    const int pair0 = blockIdx.x * 64;
    ((float4*)xs)[tid] = ((const float4*)(x + (size_t)pair0 * IND))[tid];
    __syncthreads();

    float* outp = g_fx + (size_t)pair0 * HN + tid;
#pragma unroll 4
    for (int k = 0; k < 64; k++) {
        const float* xk = xs + k * IND;
        float acc = 0.0f;
#pragma unroll
        for (int i = 0; i < IND; i++) acc = __fmaf_rn(w[i], xk[i], acc);
        outp[(size_t)k * HN] = acc;
    }
}

// ---------------------------------------------------------------------------
// Kernel 2: Wr[h][j] via sequential-p chain (bit-locked), h/j-pair interleaved.
// ---------------------------------------------------------------------------
__global__ void __launch_bounds__(512, 1)
wr_kernel(const float* __restrict__ pin, const float* __restrict__ pout,
          const float* __restrict__ l) {
    __shared__ float lp[PN];
    const int h = blockIdx.x;
    const int j = threadIdx.x;
    if (j < PN) lp[j] = __fmul_rn(l[j], pin[h * PN + j]);
    __syncthreads();

    const float* pr = pout + j * PN;
    float acc = 0.0f;
#pragma unroll
    for (int p = 0; p < PN; p++) acc = __fmaf_rn(lp[p], pr[p], acc);

    const size_t q4 = (size_t)(j >> 1) * 256 + (h >> 1);
    g_wr2[q4 * 4 + (h & 1) + 2 * (j & 1)] = acc;
}

// ---------------------------------------------------------------------------
// Kernel 3: scan. PLAIN grid (no clusters). Group of 8 CTAs = 8 batches;
// CTA u holds Wr rows h in [u*64, u*64+64) in SMEM (128 KB).
// Thread = (h-pair, batch-pair). r exchanged per step through L2 with a
// software flag barrier (release STG / acquire-spin), NOT barrier.cluster.
// ---------------------------------------------------------------------------
__global__ void __launch_bounds__(128, 1)
snn_kernel(const float* __restrict__ Wout, float* __restrict__ out,
           float arg_ls, float arg_lm, float arg_ld,
           float rgain, float dtc, float tref)
{
    extern __shared__ __align__(16) unsigned char smraw[];
    ulonglong2* wr2_s = (ulonglong2*)smraw;                      // 8192 x 16B
    ull (*rdup)[8][HN] = (ull(*)[8][HN])(smraw + 131072);        // [2][8][512]
    float* wout_sh = (float*)(smraw + 196608);                   // 4096 floats
    float* part_y  = (float*)(smraw + 212992);                   // 64 floats

    const int tid = threadIdx.x;
    const unsigned u = blockIdx.x & 7;     // slice rank within group
    const int cl   = blockIdx.x >> 3;      // group id
    const int base = cl * 8;               // first batch of this group

    const float ls  = expf(arg_ls);
    const float lm  = expf(arg_lm);
    const float ldc = expf(arg_ld);
    const float olm = 1.0f - lm;

    // lane layout: warp w holds hp = w*8 + (ln&7), bp = ln>>3
    const int w  = tid >> 5, ln = tid & 31;
    const int hp = w * 8 + (ln & 7);       // 0..31 (local h-pair)
    const int bp = ln >> 3;                // 0..3  (batch pair)
    const int hg0 = (int)u * 64 + 2 * hp;  // global h of lane-low

    // stage Wr slice (rows u*64 .. u*64+63), j2-major: wr2_s[j2*32 + hp]
    {
        const ulonglong2* gw = (const ulonglong2*)g_wr2;
        for (int i = tid; i < 8192; i += 128) {
            int j2 = i >> 5, ll = i & 31;
            wr2_s[i] = gw[(size_t)j2 * 256 + u * 32 + ll];
        }
    }
    for (int i = tid; i < HN * ON; i += 128)
        wout_sh[i] = Wout[(i & 7) * HN + (i >> 3)];
    // zero parity-0 r buffers (all 8 batches)
    for (int i = tid; i < 8 * HN; i += 128) ((ull*)rdup)[i] = 0ull;

    // neuron state: [hh][bb]
    float I[2][2]   = {{0.f,0.f},{0.f,0.f}};
    float mem[2][2] = {{0.f,0.f},{0.f,0.f}};
    float s[2][2]   = {{0.f,0.f},{0.f,0.f}};
    float r[2][2]   = {{0.f,0.f},{0.f,0.f}};
    float tl[2][2]  = {{-1.f,-1.f},{-1.f,-1.f}};

    const int b0g = base + 2 * bp, b1g = b0g + 1;
    const float2* fx0 = (const float2*)(g_fx + (size_t)b0g * HN + hg0);
    const float2* fx1 = (const float2*)(g_fx + (size_t)b1g * HN + hg0);
    float2 fxc0 = fx0[0], fxc1 = fx1[0];

    float* gr_cl = g_r + (size_t)cl * 2 * 8 * HN;   // this group's buffer

    __syncthreads();

#pragma unroll 1
    for (int t = 0; t < TS; t++) {
        const int par = t & 1, pn = par ^ 1;
        const int tn = (t < TS - 1) ? t + 1 : t;
        const float2 fxn0 = fx0[(size_t)tn * (BN * HN / 2)];
        const float2 fxn1 = fx1[(size_t)tn * (BN * HN / 2)];

        // two FFMA2 chains, sequential in j (bit-exact vs scalar chain)
        const ulonglong2* d0 = (const ulonglong2*)&rdup[par][2 * bp][0];
        const ulonglong2* d1 = (const ulonglong2*)&rdup[par][2 * bp + 1][0];
        ull rec_b0 = 0ull, rec_b1 = 0ull;
#pragma unroll 8
        for (int j2 = 0; j2 < 256; j2++) {
            const ulonglong2 q  = wr2_s[j2 * 32 + hp];
            const ulonglong2 r0 = d0[j2];
            const ulonglong2 r1 = d1[j2];
            rec_b0 = ffma2(q.x, r0.x, rec_b0);
            rec_b0 = ffma2(q.y, r0.y, rec_b0);
            rec_b1 = ffma2(q.x, r1.x, rec_b1);
            rec_b1 = ffma2(q.y, r1.y, rec_b1);
        }
        float rec[2][2], fxv[2][2];
        unpk2(rec_b0, rec[0][0], rec[1][0]);
        unpk2(rec_b1, rec[0][1], rec[1][1]);
        fxv[0][0] = fxc0.x; fxv[1][0] = fxc0.y;
        fxv[0][1] = fxc1.x; fxv[1][1] = fxc1.y;

        const float ti = __fmul_rn(dtc, (float)t);
#pragma unroll
        for (int hh = 0; hh < 2; hh++)
#pragma unroll
            for (int bb = 0; bb < 2; bb++) {
                I[hh][bb] = __fadd_rn(__fadd_rn(__fmul_rn(ls, I[hh][bb]),
                                                fxv[hh][bb]), rec[hh][bb]);
                const float notref = (ti > __fadd_rn(tl[hh][bb], tref)) ? 1.0f : 0.0f;
                const float memn = __fmul_rn(__fmul_rn(notref,
                        __fadd_rn(__fmul_rn(lm, mem[hh][bb]),
                                  __fmul_rn(olm, I[hh][bb]))),
                        __fsub_rn(1.0f, s[hh][bb]));
                r[hh][bb] = __fadd_rn(__fmul_rn(ldc, r[hh][bb]),
                                      __fmul_rn(rgain, s[hh][bb]));
                const float snew = (__fsub_rn(memn, 1.0f) > 0.0f) ? 1.0f : 0.0f;
                tl[hh][bb] = __fadd_rn(tl[hh][bb],
                               __fmul_rn(__fsub_rn(ti, tl[hh][bb]), snew));
                mem[hh][bb] = memn; s[hh][bb] = snew;
            }
        fxc0 = fxn0; fxc1 = fxn1;

        // publish r(t): 2 coalesced STG.64 into this group's L2 buffer
        {
            float* dst = gr_cl + ((size_t)pn * 8 + 2 * bp) * HN + hg0;
            *(float2*)dst        = make_float2(r[0][0], r[1][0]);
            *(float2*)(dst + HN) = make_float2(r[0][1], r[1][1]);
        }

        // ---- software group barrier through L2 ----
        __threadfence();            // make all threads' STGs gpu-visible
        __syncthreads();            // order tid0's flag store after them
        if (tid == 0) {
            unsigned* f = &g_sync[cl][u * 32];
            asm volatile("st.release.gpu.global.u32 [%0], %1;"
                         :: "l"(f), "r"((unsigned)(t + 1)) : "memory");
        }
        if (tid < 8) {
            const unsigned* f = &g_sync[cl][tid * 32];
            unsigned v;
            do {
                asm volatile("ld.acquire.gpu.global.u32 %0, [%1];"
                             : "=r"(v) : "l"(f) : "memory");
            } while (v < (unsigned)(t + 1));
        }
        __syncthreads();            // acquires visible to whole CTA

        // pull full r-set (8 batches x 512 h = 16 KB) from L2, store dup pairs
        {
            const float4* src = (const float4*)(gr_cl + (size_t)pn * 8 * HN);
            float4 v[8];
#pragma unroll
            for (int i = 0; i < 8; i++) v[i] = __ldcg(src + tid + i * 128);
            ulonglong2* dst2 = (ulonglong2*)&rdup[pn][0][0];
#pragma unroll
            for (int i = 0; i < 8; i++) {
                const int idx = tid + i * 128;
                dst2[idx * 2 + 0] = make_ulonglong2(pk2(v[i].x, v[i].x),
                                                    pk2(v[i].y, v[i].y));
                dst2[idx * 2 + 1] = make_ulonglong2(pk2(v[i].z, v[i].z),
                                                    pk2(v[i].w, v[i].w));
            }
        }
        __syncthreads();   // rdup[pn] complete

        // y for batch (base+u) from full r(t) (same order as R6..R9)
        if (tid < 64) {
            const int o = tid & 7, seg = tid >> 3;
            const float* wq = wout_sh + (seg << 6) * 8 + o;
            const float* rr = (const float*)&rdup[pn][u][seg << 6];
            float e0 = 0.0f, e1 = 0.0f;
#pragma unroll
            for (int hh = 0; hh < 64; hh += 2) {
                e0 = __fmaf_rn(wq[hh << 3],       rr[hh * 2],       e0);
                e1 = __fmaf_rn(wq[(hh + 1) << 3], rr[(hh + 1) * 2], e1);
            }
            part_y[tid] = e0 + e1;
        }
        __syncthreads();
        if (tid < ON) {
            const float* q = part_y + tid;
            float v = ((q[0] + q[8]) + (q[16] + q[24])) +
                      ((q[32] + q[40]) + (q[48] + q[56]));
            out[((size_t)t * BN + base + u) * ON + tid] = v;
        }
    }

    // ---- reset barrier state for deterministic graph replay ----
    __syncthreads();
    if (tid == 0) {
        // last CTA of the group to finish resets all flags
        unsigned old = atomicAdd(&g_fin[cl * 32], 1u);
        if (old == 7u) {
#pragma unroll
            for (int k = 0; k < 8; k++) g_sync[cl][k * 32] = 0u;
            __threadfence();
            g_fin[cl * 32] = 0u;
        }
    }
}

extern "C" void kernel_launch(void* const* d_in, const int* in_sizes, int n_in,
                              void* d_out, int out_size) {
    const float* x    = (const float*)d_in[0];
    const float* Win  = (const float*)d_in[1];
    const float* Wout = (const float*)d_in[2];
    const float* pin  = (const float*)d_in[3];
    const float* pout = (const float*)d_in[4];
    const float* l    = (const float*)d_in[5];
    float* out = (float*)d_out;

    const float arg_ls = (float)(-0.002 / 0.01);
    const float arg_lm = (float)(-0.002 / 0.02);
    const float arg_ld = (float)(-0.002 / 0.03);
    const float rgain  = (float)(0.002 / 0.03);
    const float dtc    = (float)0.002;
    const float tref   = (float)(5.0 * 0.002);

    const int smem_bytes = 131072 + 65536 + 16384 + 256;   // 213248
    cudaFuncSetAttribute(snn_kernel, cudaFuncAttributeMaxDynamicSharedMemorySize,
                         smem_bytes);

    fx_kernel<<<(TS * BN) / 64, 512>>>(x, Win);
    wr_kernel<<<HN, 512>>>(pin, pout, l);
    snn_kernel<<<BN, 128, smem_bytes>>>(Wout, out, arg_ls, arg_lm, arg_ld,
                                        rgain, dtc, tref);
}